// round 3
// baseline (speedup 1.0000x reference)
#include <cuda_runtime.h>
#include <math.h>

#define BB 128
#define HH 512
#define FF 16
#define HIDD 64
#define NFF 257
#define KDIM (NFF*HIDD)   // 16448
#define MG (BB*FF)        // 2048

// ---------------- device scratch (no allocs allowed) ----------------
static __device__ float g_s[BB*HH];
static __device__ float g_csdRe[BB*NFF];
static __device__ float g_csdIm[BB*NFF];
static __device__ float g_fftRe[BB*NFF*FF];
static __device__ float g_fftIm[BB*NFF*FF];
static __device__ float g_proj[(size_t)MG*KDIM];   // [m=b*16+f][k*64+h]  ~135MB
static __device__ float g_w[MG*NFF];
static __device__ float g_wfRe[BB*NFF*FF];
static __device__ float g_wfIm[BB*NFF*FF];

// ---------------- K0: s[b,t] = sum_f x ----------------
__global__ __launch_bounds__(256) void k0_sum(const float* __restrict__ x){
    int i = blockIdx.x*256 + threadIdx.x;
    if(i < BB*HH){
        const float4* p = reinterpret_cast<const float4*>(x) + (size_t)i*4;
        float a = 0.f;
        #pragma unroll
        for(int j=0;j<4;j++){ float4 v = p[j]; a += v.x+v.y+v.z+v.w; }
        g_s[i] = a;
    }
}

// ---------------- K1: autocorr('same') + rfft -> csd[b,k] ----------------
__global__ __launch_bounds__(256) void k1_csd(){
    __shared__ float s_sh[HH];
    __shared__ float c_sh[HH];
    __shared__ float ct[HH];
    int b = blockIdx.x, tid = threadIdx.x;
    for(int i=tid;i<HH;i+=256){
        s_sh[i] = g_s[b*HH+i];
        ct[i]   = cospif((float)i * (1.0f/256.0f));   // cos(2*pi*i/512)
    }
    __syncthreads();
    for(int t=tid;t<HH;t+=256){
        int l = t - 255;                               // lag
        int lo = l < 0 ? -l : 0;
        int hi = l < 0 ? HH : HH - l;
        float acc = 0.f;
        for(int tau=lo;tau<hi;tau++) acc += s_sh[tau]*s_sh[tau+l];
        c_sh[t] = acc;
    }
    __syncthreads();
    const float scale = 1.0f/(256.0f * 22.62741699796952f);  // 1/(F^2 * sqrt(512))
    for(int k=tid;k<NFF;k+=256){
        float ar=0.f, ai=0.f;
        int idx=0, step=k & 511;
        for(int t=0;t<HH;t++){
            float c = c_sh[t];
            ar += c*ct[idx];
            ai -= c*ct[(idx+384)&511];                 // sin via cos shift
            idx = (idx+step)&511;
        }
        g_csdRe[b*NFF+k] = ar*scale;
        g_csdIm[b*NFF+k] = ai*scale;
    }
}

// ---------------- K2: rfft(x) ortho + csd -> fft[b,k,f] ----------------
__global__ __launch_bounds__(256) void k2_fft(const float* __restrict__ x){
    __shared__ float xs[HH*FF];  // 32KB
    __shared__ float ct[HH];
    int b = blockIdx.x, tid = threadIdx.x;
    {
        const float4* src = reinterpret_cast<const float4*>(x + (size_t)b*HH*FF);
        float4* dst = reinterpret_cast<float4*>(xs);
        for(int i=tid;i<HH*FF/4;i+=256) dst[i]=src[i];
        for(int i=tid;i<HH;i+=256) ct[i]=cospif((float)i*(1.0f/256.0f));
    }
    __syncthreads();
    int f = tid & 15, kg = tid >> 4;   // kg in [0,16)
    float ar[17], ai[17];
    #pragma unroll
    for(int i=0;i<17;i++){ ar[i]=0.f; ai[i]=0.f; }
    for(int t=0;t<HH;t++){
        float xv = xs[t*FF+f];
        int idx  = (kg*t)&511;
        int step = (t<<4)&511;
        #pragma unroll
        for(int i=0;i<17;i++){
            ar[i] = fmaf(xv, ct[idx], ar[i]);
            ai[i] = fmaf(-xv, ct[(idx+384)&511], ai[i]);
            idx = (idx+step)&511;
        }
    }
    const float sc = 0.044194173824159216f;  // 1/sqrt(512)
    #pragma unroll
    for(int i=0;i<17;i++){
        int k = kg + (i<<4);
        if(k < NFF){
            int o = (b*NFF+k)*FF+f;
            g_fftRe[o] = ar[i]*sc + g_csdRe[b*NFF+k];
            g_fftIm[o] = ai[i]*sc + g_csdIm[b*NFF+k];
        }
    }
}

// ---------------- K3: features + shared projection (relu) ----------------
__global__ __launch_bounds__(256) void k3_proj(const float* __restrict__ Wp, const float* __restrict__ bp){
    __shared__ float ws[4*HIDD];
    __shared__ float bs[HIDD];
    int tid = threadIdx.x;
    if(tid < 4*HIDD) ws[tid] = Wp[tid];
    if(tid < HIDD)   bs[tid] = bp[tid];
    __syncthreads();
    int gidx = blockIdx.x*256 + tid;       // over (b*NF+k)*F+f  (== fft linear idx)
    if(gidx >= BB*NFF*FF) return;
    int f  = gidx & 15;
    int t2 = gidx >> 4;
    int k  = t2 % NFF, b = t2 / NFF;
    float re = g_fftRe[gidx], im = g_fftIm[gidx];
    float mag = sqrtf(re*re + im*im);
    float sa, ca;
    if(mag > 0.f){ float inv = 1.0f/mag; sa = im*inv; ca = re*inv; }
    else         { sa = 0.f; ca = 1.f; }
    float fr = (float)k * (100.0f/512.0f);
    float4* dst = reinterpret_cast<float4*>(&g_proj[((size_t)(b*FF+f)*NFF + k)*HIDD]);
    #pragma unroll
    for(int h4=0; h4<16; h4++){
        float4 o;
        int h = h4*4;
        o.x = fmaxf(fmaf(mag, ws[h+0], fmaf(sa, ws[64+h+0], fmaf(ca, ws[128+h+0], fmaf(fr, ws[192+h+0], bs[h+0])))), 0.f);
        o.y = fmaxf(fmaf(mag, ws[h+1], fmaf(sa, ws[64+h+1], fmaf(ca, ws[128+h+1], fmaf(fr, ws[192+h+1], bs[h+1])))), 0.f);
        o.z = fmaxf(fmaf(mag, ws[h+2], fmaf(sa, ws[64+h+2], fmaf(ca, ws[128+h+2], fmaf(fr, ws[192+h+2], bs[h+2])))), 0.f);
        o.w = fmaxf(fmaf(mag, ws[h+3], fmaf(sa, ws[64+h+3], fmaf(ca, ws[128+h+3], fmaf(fr, ws[192+h+3], bs[h+3])))), 0.f);
        dst[h4] = o;
    }
}

// ---------------- K4: gate GEMM (M=2048,K=16448,N=257) + SiLU + sigmoid ----------------
__global__ __launch_bounds__(128) void k4_gate(const float* __restrict__ Wg, const float* __restrict__ bg){
    __shared__ float As[32][64];   // [k][m] with XOR swizzle on m
    __shared__ float Bs[32][32];
    int tid = threadIdx.x;
    int m0 = blockIdx.x*64, n0 = blockIdx.y*32;
    int tx = tid & 7, ty = tid >> 3;
    float acc[4][4];
    #pragma unroll
    for(int i=0;i<4;i++)
        #pragma unroll
        for(int j=0;j<4;j++) acc[i][j]=0.f;

    for(int kt=0; kt<KDIM; kt+=32){
        #pragma unroll
        for(int r=0;r<4;r++){
            int q   = tid + r*128;
            int row = q >> 3;
            int kq  = (q & 7) << 2;
            float4 v = *reinterpret_cast<const float4*>(&g_proj[(size_t)(m0+row)*KDIM + kt + kq]);
            As[kq+0][row ^ ((kq+0)&28)] = v.x;
            As[kq+1][row ^ ((kq+1)&28)] = v.y;
            As[kq+2][row ^ ((kq+2)&28)] = v.z;
            As[kq+3][row ^ ((kq+3)&28)] = v.w;
        }
        #pragma unroll
        for(int r=0;r<8;r++){
            int e = r*128 + tid;
            int row = e >> 5, col = e & 31;
            int n = n0 + col;
            Bs[row][col] = (n < NFF) ? Wg[(size_t)(kt+row)*NFF + n] : 0.f;
        }
        __syncthreads();
        #pragma unroll
        for(int k=0;k<32;k++){
            float4 av = *reinterpret_cast<const float4*>(&As[k][(ty<<2) ^ (k&28)]);
            float4 bv = *reinterpret_cast<const float4*>(&Bs[k][tx<<2]);
            float a[4]  = {av.x,av.y,av.z,av.w};
            float bb[4] = {bv.x,bv.y,bv.z,bv.w};
            #pragma unroll
            for(int i=0;i<4;i++)
                #pragma unroll
                for(int j=0;j<4;j++) acc[i][j] = fmaf(a[i], bb[j], acc[i][j]);
        }
        __syncthreads();
    }
    #pragma unroll
    for(int i=0;i<4;i++){
        int m = m0 + (ty<<2) + i;
        #pragma unroll
        for(int j=0;j<4;j++){
            int n = n0 + (tx<<2) + j;
            if(n < NFF){
                float gg = acc[i][j] + bg[n];
                float s1 = 1.f/(1.f + expf(-gg));
                float g2 = gg*s1;                     // SiLU
                g_w[m*NFF+n] = 1.f/(1.f + expf(-g2)); // gate weight
            }
        }
    }
}

// ---------------- K5: complexifier + blend -> wf[b,k,f] ----------------
__global__ __launch_bounds__(256) void k5_blend(const float* __restrict__ mw, const float* __restrict__ mb,
                                                const float* __restrict__ pw, const float* __restrict__ pb){
    int gidx = blockIdx.x*256 + threadIdx.x;   // m*NFF + k
    if(gidx >= MG*NFF) return;
    int k = gidx % NFF;
    int m = gidx / NFF;
    int f = m & 15, b = m >> 4;
    const float4* p4  = reinterpret_cast<const float4*>(&g_proj[((size_t)m*NFF + k)*HIDD]);
    const float4* mw4 = reinterpret_cast<const float4*>(&mw[(size_t)k*HIDD]);
    const float4* pw4 = reinterpret_cast<const float4*>(&pw[(size_t)k*HIDD]);
    float dm = 0.f, dp = 0.f;
    #pragma unroll
    for(int h=0;h<16;h++){
        float4 a = p4[h], u = mw4[h], v = pw4[h];
        dm = fmaf(a.x,u.x, fmaf(a.y,u.y, fmaf(a.z,u.z, fmaf(a.w,u.w, dm))));
        dp = fmaf(a.x,v.x, fmaf(a.y,v.y, fmaf(a.z,v.z, fmaf(a.w,v.w, dp))));
    }
    float mval = fmaxf(dm + mb[k], 0.f);
    float ph = 6.283185307179586f / (1.f + expf(-(dp + pb[k])));
    float sp, cp;
    sincosf(ph, &sp, &cp);
    float w = g_w[m*NFF + k];
    int fidx = (b*NFF + k)*FF + f;
    float fre = g_fftRe[fidx], fim = g_fftIm[fidx];
    g_wfRe[fidx] = fmaf(w, mval*cp - fre, fre);
    g_wfIm[fidx] = fmaf(w, mval*sp - fim, fim);
}

// ---------------- K6: irfft(ortho) + residual + LayerNorm ----------------
__global__ __launch_bounds__(256) void k6_irfft(const float* __restrict__ x,
                                                const float* __restrict__ gamma_, const float* __restrict__ beta_,
                                                float* __restrict__ out){
    __shared__ float wr_sh[NFF*FF];
    __shared__ float wi_sh[NFF*FF];
    __shared__ float ct[HH];
    int b = blockIdx.x, tid = threadIdx.x;
    const float sc = 0.044194173824159216f;  // 1/sqrt(512)
    for(int i=tid;i<NFF*FF;i+=256){
        int k = i / FF;
        float alpha = (k==0 || k==256) ? sc : 2.0f*sc;
        wr_sh[i] = g_wfRe[b*NFF*FF + i] * alpha;
        wi_sh[i] = g_wfIm[b*NFF*FF + i] * alpha;
    }
    for(int i=tid;i<HH;i+=256) ct[i]=cospif((float)i*(1.0f/256.0f));
    __syncthreads();
    int f = tid & 15, tg = tid >> 4;   // tg in [0,16), t = tg + 16*i
    float acc[32];
    #pragma unroll
    for(int i=0;i<32;i++) acc[i]=0.f;
    for(int k=0;k<NFF;k++){
        float wr = wr_sh[k*FF+f], wi = wi_sh[k*FF+f];
        int idx  = (k*tg)&511;
        int step = (k<<4)&511;
        #pragma unroll
        for(int i=0;i<32;i++){
            // Re(X_k e^{+i theta}) = wr*cos - wi*sin ; sin==0 at k=0,256 discards their imag
            acc[i] = fmaf(wr, ct[idx], fmaf(-wi, ct[(idx+384)&511], acc[i]));
            idx = (idx+step)&511;
        }
    }
    float gm = gamma_[f], bt = beta_[f];
    #pragma unroll
    for(int i=0;i<32;i++){
        int t = tg + (i<<4);
        float y = acc[i] + x[((size_t)b*HH + t)*FF + f];
        float s = y, s2 = y*y;
        #pragma unroll
        for(int off=8; off>0; off>>=1){
            s  += __shfl_xor_sync(0xffffffffu, s,  off, 16);
            s2 += __shfl_xor_sync(0xffffffffu, s2, off, 16);
        }
        float mu  = s  * (1.0f/16.0f);
        float var = s2 * (1.0f/16.0f) - mu*mu;
        out[((size_t)b*HH + t)*FF + f] = (y - mu) * rsqrtf(var + 1e-5f) * gm + bt;
    }
}

// ---------------- launch ----------------
extern "C" void kernel_launch(void* const* d_in, const int* in_sizes, int n_in,
                              void* d_out, int out_size){
    const float* x   = (const float*)d_in[0];
    const float* Wp  = (const float*)d_in[1];
    const float* bp  = (const float*)d_in[2];
    const float* Wg  = (const float*)d_in[3];
    const float* bg  = (const float*)d_in[4];
    const float* mw  = (const float*)d_in[5];
    const float* mb  = (const float*)d_in[6];
    const float* pw  = (const float*)d_in[7];
    const float* pb  = (const float*)d_in[8];
    const float* gam = (const float*)d_in[9];
    const float* bet = (const float*)d_in[10];
    float* out = (float*)d_out;

    k0_sum <<<(BB*HH+255)/256, 256>>>(x);
    k1_csd <<<BB, 256>>>();
    k2_fft <<<BB, 256>>>(x);
    k3_proj<<<(BB*NFF*FF+255)/256, 256>>>(Wp, bp);
    dim3 g4(MG/64, (NFF+31)/32);
    k4_gate<<<g4, 128>>>(Wg, bg);
    k5_blend<<<(MG*NFF+255)/256, 256>>>(mw, mb, pw, pb);
    k6_irfft<<<BB, 256>>>(x, gam, bet, out);
}

// round 6
// speedup vs baseline: 1.9867x; 1.9867x over previous
#include <cuda_runtime.h>
#include <cuda_bf16.h>
#include <math.h>
#include <cstdint>

#define BB 128
#define HH 512
#define FF 16
#define HIDD 64
#define NFF 257
#define KDIM (NFF*HIDD)   // 16448
#define MG (BB*FF)        // 2048
#define NB 264            // padded N (257 -> 264 = 3*88)

// ---------------- device scratch (no allocs allowed) ----------------
static __device__ float g_s[BB*HH];
static __device__ float g_csdRe[BB*NFF];
static __device__ float g_csdIm[BB*NFF];
static __device__ float g_fftRe[BB*NFF*FF];
static __device__ float g_fftIm[BB*NFF*FF];
static __device__ __align__(256) __nv_bfloat16 g_projbf[(size_t)MG*KDIM];  // ~67MB, A operand [m][K]
static __device__ __align__(256) __nv_bfloat16 g_WgT[(size_t)NB*KDIM];     // ~8.7MB, B^T operand [n][K]
static __device__ float g_w[MG*NFF];
static __device__ float g_wfRe[BB*NFF*FF];
static __device__ float g_wfIm[BB*NFF*FF];

// ---------------- PTX helpers (base-target ISA only) ----------------
__device__ __forceinline__ uint32_t smem_u32(const void* p){
    uint32_t a;
    asm("{ .reg .u64 t; cvta.to.shared.u64 t, %1; cvt.u32.u64 %0, t; }" : "=r"(a) : "l"(p));
    return a;
}
#define CP_ASYNC16(s,g) asm volatile("cp.async.cg.shared.global [%0], [%1], 16;" :: "r"(s), "l"(g))
#define CP_COMMIT()     asm volatile("cp.async.commit_group;" ::: "memory")
#define CP_WAIT1()      asm volatile("cp.async.wait_group 1;" ::: "memory")

__device__ __forceinline__ void ldsm4(uint32_t& r0, uint32_t& r1, uint32_t& r2, uint32_t& r3, uint32_t a){
    asm volatile("ldmatrix.sync.aligned.m8n8.x4.shared.b16 {%0,%1,%2,%3}, [%4];"
                 : "=r"(r0), "=r"(r1), "=r"(r2), "=r"(r3) : "r"(a));
}
__device__ __forceinline__ void ldsm2(uint32_t& r0, uint32_t& r1, uint32_t a){
    asm volatile("ldmatrix.sync.aligned.m8n8.x2.shared.b16 {%0,%1}, [%2];"
                 : "=r"(r0), "=r"(r1) : "r"(a));
}
__device__ __forceinline__ void mma16816(float* c, uint32_t a0, uint32_t a1, uint32_t a2, uint32_t a3,
                                         uint32_t b0, uint32_t b1){
    asm volatile("mma.sync.aligned.m16n8k16.row.col.f32.bf16.bf16.f32 "
                 "{%0,%1,%2,%3}, {%4,%5,%6,%7}, {%8,%9}, {%0,%1,%2,%3};"
                 : "+f"(c[0]), "+f"(c[1]), "+f"(c[2]), "+f"(c[3])
                 : "r"(a0), "r"(a1), "r"(a2), "r"(a3), "r"(b0), "r"(b1));
}

// ---------------- K0: s[b,t] = sum_f x ----------------
__global__ __launch_bounds__(256) void k0_sum(const float* __restrict__ x){
    int i = blockIdx.x*256 + threadIdx.x;
    if(i < BB*HH){
        const float4* p = reinterpret_cast<const float4*>(x) + (size_t)i*4;
        float a = 0.f;
        #pragma unroll
        for(int j=0;j<4;j++){ float4 v = p[j]; a += v.x+v.y+v.z+v.w; }
        g_s[i] = a;
    }
}

// ---------------- K1: autocorr('same') + rfft -> csd[b,k] ----------------
__global__ __launch_bounds__(256) void k1_csd(){
    __shared__ float s_sh[HH];
    __shared__ float c_sh[HH];
    __shared__ float ct[HH];
    int b = blockIdx.x, tid = threadIdx.x;
    for(int i=tid;i<HH;i+=256){
        s_sh[i] = g_s[b*HH+i];
        ct[i]   = cospif((float)i * (1.0f/256.0f));
    }
    __syncthreads();
    for(int t=tid;t<HH;t+=256){
        int l = t - 255;
        int lo = l < 0 ? -l : 0;
        int hi = l < 0 ? HH : HH - l;
        float acc = 0.f;
        for(int tau=lo;tau<hi;tau++) acc += s_sh[tau]*s_sh[tau+l];
        c_sh[t] = acc;
    }
    __syncthreads();
    const float scale = 1.0f/(256.0f * 22.62741699796952f);
    for(int k=tid;k<NFF;k+=256){
        float ar=0.f, ai=0.f;
        int idx=0, step=k & 511;
        for(int t=0;t<HH;t++){
            float c = c_sh[t];
            ar += c*ct[idx];
            ai -= c*ct[(idx+384)&511];
            idx = (idx+step)&511;
        }
        g_csdRe[b*NFF+k] = ar*scale;
        g_csdIm[b*NFF+k] = ai*scale;
    }
}

// ---------------- K2: rfft(x) ortho + csd -> fft[b,k,f] ----------------
__global__ __launch_bounds__(256) void k2_fft(const float* __restrict__ x){
    __shared__ float xs[HH*FF];
    __shared__ float ct[HH];
    int b = blockIdx.x, tid = threadIdx.x;
    {
        const float4* src = reinterpret_cast<const float4*>(x + (size_t)b*HH*FF);
        float4* dst = reinterpret_cast<float4*>(xs);
        for(int i=tid;i<HH*FF/4;i+=256) dst[i]=src[i];
        for(int i=tid;i<HH;i+=256) ct[i]=cospif((float)i*(1.0f/256.0f));
    }
    __syncthreads();
    int f = tid & 15, kg = tid >> 4;
    float ar[17], ai[17];
    #pragma unroll
    for(int i=0;i<17;i++){ ar[i]=0.f; ai[i]=0.f; }
    for(int t=0;t<HH;t++){
        float xv = xs[t*FF+f];
        int idx  = (kg*t)&511;
        int step = (t<<4)&511;
        #pragma unroll
        for(int i=0;i<17;i++){
            ar[i] = fmaf(xv, ct[idx], ar[i]);
            ai[i] = fmaf(-xv, ct[(idx+384)&511], ai[i]);
            idx = (idx+step)&511;
        }
    }
    const float sc = 0.044194173824159216f;
    #pragma unroll
    for(int i=0;i<17;i++){
        int k = kg + (i<<4);
        if(k < NFF){
            int o = (b*NFF+k)*FF+f;
            g_fftRe[o] = ar[i]*sc + g_csdRe[b*NFF+k];
            g_fftIm[o] = ai[i]*sc + g_csdIm[b*NFF+k];
        }
    }
}

// ---------------- K3: features + shared projection -> bf16 A operand ----------------
__global__ __launch_bounds__(256) void k3_proj(const float* __restrict__ Wp, const float* __restrict__ bp){
    __shared__ float ws[4*HIDD];
    __shared__ float bs[HIDD];
    int tid = threadIdx.x;
    if(tid < 4*HIDD) ws[tid] = Wp[tid];
    if(tid < HIDD)   bs[tid] = bp[tid];
    __syncthreads();
    int gidx = blockIdx.x*256 + tid;
    if(gidx >= BB*NFF*FF) return;
    int f  = gidx & 15;
    int t2 = gidx >> 4;
    int k  = t2 % NFF, b = t2 / NFF;
    float re = g_fftRe[gidx], im = g_fftIm[gidx];
    float mag = sqrtf(re*re + im*im);
    float sa, ca;
    if(mag > 0.f){ float inv = 1.0f/mag; sa = im*inv; ca = re*inv; }
    else         { sa = 0.f; ca = 1.f; }
    float fr = (float)k * (100.0f/512.0f);
    int m = b*FF + f;
    uint4* dst = reinterpret_cast<uint4*>(g_projbf + (size_t)m*KDIM + (size_t)k*HIDD);
    #pragma unroll
    for(int q=0;q<8;q++){
        float o[8];
        #pragma unroll
        for(int e=0;e<8;e++){
            int h = q*8+e;
            o[e] = fmaxf(fmaf(mag, ws[h], fmaf(sa, ws[64+h], fmaf(ca, ws[128+h], fmaf(fr, ws[192+h], bs[h])))), 0.f);
        }
        union { __nv_bfloat162 h2[4]; uint4 v; } u;
        u.h2[0] = __floats2bfloat162_rn(o[0], o[1]);
        u.h2[1] = __floats2bfloat162_rn(o[2], o[3]);
        u.h2[2] = __floats2bfloat162_rn(o[4], o[5]);
        u.h2[3] = __floats2bfloat162_rn(o[6], o[7]);
        dst[q] = u.v;
    }
}

// ---------------- K4t: transpose Wg [K,N] fp32 -> WgT [NB,K] bf16 (pad rows zero) ----------------
__global__ __launch_bounds__(256) void k4t(const float* __restrict__ Wg){
    __shared__ float t[32][33];
    int tid = threadIdx.x;
    int tx = tid & 31, ty = tid >> 5;
    int k0 = blockIdx.x*32, n0 = blockIdx.y*32;
    for(int r=ty; r<32; r+=8){
        int n = n0 + tx;
        t[r][tx] = (n < NFF) ? Wg[(size_t)(k0+r)*NFF + n] : 0.f;
    }
    __syncthreads();
    for(int r=ty; r<32; r+=8){
        int n = n0 + r;
        if(n < NB) g_WgT[(size_t)n*KDIM + k0 + tx] = __float2bfloat16(t[tx][r]);
    }
}

// ---------------- K4: bf16 mma.sync GEMM + bias + SiLU + sigmoid ----------------
// BM=64, BN=88, BK=64, 3 stages, 128 threads (4 warps, each m16 x n88)
#define BM4 64
#define BN4 88
#define S4 3
#define A4_BYTES (BM4*128)          // 8192
#define B4_BYTES (BN4*128)          // 11264
#define STG4 (A4_BYTES + B4_BYTES)  // 19456
#define SMEM_K4 (1024 + S4*STG4)

__global__ __launch_bounds__(128) void k4_gemm(const float* __restrict__ bg){
    extern __shared__ char smem_raw[];
    uint32_t sb = (smem_u32(smem_raw) + 1023u) & ~1023u;
    int tid = threadIdx.x, w = tid >> 5, lane = tid & 31;
    int m0 = blockIdx.x*BM4, n0 = blockIdx.y*BN4;

    const __nv_bfloat16* Ab = g_projbf + (size_t)m0*KDIM;
    const __nv_bfloat16* Bb = g_WgT   + (size_t)n0*KDIM;

    auto load_chunk = [&](int c, int slot){
        uint32_t abuf = sb + (uint32_t)slot*STG4;
        uint32_t bbuf = abuf + A4_BYTES;
        for(int i=tid; i<(BM4+BN4)*8; i+=128){
            uint32_t dst; const __nv_bfloat16* src;
            if(i < BM4*8){
                int row = i >> 3, j = i & 7;
                uint32_t off = (uint32_t)((row<<7) | (j<<4));
                dst = abuf + (off ^ ((off>>3)&0x70));
                src = Ab + (size_t)row*KDIM + c*64 + j*8;
            } else {
                int ib = i - BM4*8;
                int row = ib >> 3, j = ib & 7;
                uint32_t off = (uint32_t)((row<<7) | (j<<4));
                dst = bbuf + (off ^ ((off>>3)&0x70));
                src = Bb + (size_t)row*KDIM + c*64 + j*8;
            }
            CP_ASYNC16(dst, src);
        }
    };

    float acc[11][4];
    #pragma unroll
    for(int j=0;j<11;j++)
        #pragma unroll
        for(int e=0;e<4;e++) acc[j][e] = 0.f;

    // per-lane ldmatrix row/byte components
    int arow  = 16*w + (lane & 7) + ((lane >> 3) & 1)*8;  // A: m row within tile
    int abyt  = ((lane >> 4) & 1)*16;                     // A: 16B half
    int bhalf = ((lane >> 3) & 1)*16;                     // B: 16B half
    int bjoff = (lane >> 4) & 1;                          // B: paired tile select

    // prologue
    load_chunk(0, 0); CP_COMMIT();
    load_chunk(1, 1); CP_COMMIT();

    for(int c=0; c<257; c++){
        CP_WAIT1();
        __syncthreads();
        // issue next loads first (into slot (c-1)%3, already consumed by all warps)
        int cn = c + 2;
        if(cn < 257) load_chunk(cn, cn % S4);
        CP_COMMIT();

        uint32_t abuf = sb + (uint32_t)(c % S4)*STG4;
        uint32_t bbuf = abuf + A4_BYTES;
        #pragma unroll
        for(int ks=0; ks<4; ks++){
            uint32_t a0,a1,a2,a3;
            {
                uint32_t colb = (uint32_t)(abyt + ks*32);
                uint32_t addr = abuf + (uint32_t)arow*128 + (colb ^ (((uint32_t)arow & 7u)*16u));
                ldsm4(a0,a1,a2,a3, addr);
            }
            #pragma unroll
            for(int jp=0; jp<5; jp++){
                int j = jp*2;
                int brow = 8*(j + bjoff) + (lane & 7);
                uint32_t colb = (uint32_t)(bhalf + ks*32);
                uint32_t addr = bbuf + (uint32_t)brow*128 + (colb ^ (((uint32_t)brow & 7u)*16u));
                uint32_t r0,r1,r2,r3;
                ldsm4(r0,r1,r2,r3, addr);
                mma16816(acc[j],   a0,a1,a2,a3, r0,r1);
                mma16816(acc[j+1], a0,a1,a2,a3, r2,r3);
            }
            {
                int brow = 80 + (lane & 7);
                uint32_t colb = (uint32_t)(bhalf + ks*32);
                uint32_t addr = bbuf + (uint32_t)brow*128 + (colb ^ (((uint32_t)brow & 7u)*16u));
                uint32_t r0,r1;
                ldsm2(r0,r1, addr);
                mma16816(acc[10], a0,a1,a2,a3, r0,r1);
            }
        }
    }

    // epilogue: bias + SiLU + sigmoid
    int mr = m0 + 16*w + (lane >> 2);
    #pragma unroll
    for(int j=0;j<11;j++){
        int n = n0 + 8*j + (lane & 3)*2;
        #pragma unroll
        for(int e=0;e<2;e++){
            int nn = n + e;
            if(nn < NFF){
                float bias = bg[nn];
                float gg = acc[j][e] + bias;
                float s1 = 1.f/(1.f + expf(-gg));
                float g2 = gg*s1;
                g_w[mr*NFF + nn] = 1.f/(1.f + expf(-g2));
                gg = acc[j][2+e] + bias;
                s1 = 1.f/(1.f + expf(-gg));
                g2 = gg*s1;
                g_w[(mr+8)*NFF + nn] = 1.f/(1.f + expf(-g2));
            }
        }
    }
}

// ---------------- K5: recompute proj (fp32) + complexifier + blend ----------------
__global__ __launch_bounds__(256) void k5_blend(const float* __restrict__ mw, const float* __restrict__ mb,
                                                const float* __restrict__ pw, const float* __restrict__ pb,
                                                const float* __restrict__ Wp, const float* __restrict__ bp){
    __shared__ float ws[4*HIDD];
    __shared__ float bs[HIDD];
    int tid = threadIdx.x;
    if(tid < 4*HIDD) ws[tid] = Wp[tid];
    if(tid < HIDD)   bs[tid] = bp[tid];
    __syncthreads();
    int gidx = blockIdx.x*256 + tid;   // m*NFF + k
    if(gidx >= MG*NFF) return;
    int k = gidx % NFF;
    int m = gidx / NFF;
    int f = m & 15, b = m >> 4;
    int fidx = (b*NFF + k)*FF + f;
    float re = g_fftRe[fidx], im = g_fftIm[fidx];
    float mag = sqrtf(re*re + im*im);
    float sa, ca;
    if(mag > 0.f){ float inv = 1.0f/mag; sa = im*inv; ca = re*inv; }
    else         { sa = 0.f; ca = 1.f; }
    float fr = (float)k * (100.0f/512.0f);
    const float4* mw4 = reinterpret_cast<const float4*>(mw + (size_t)k*HIDD);
    const float4* pw4 = reinterpret_cast<const float4*>(pw + (size_t)k*HIDD);
    float dm = 0.f, dp = 0.f;
    #pragma unroll
    for(int h4=0; h4<16; h4++){
        float4 u = mw4[h4], v = pw4[h4];
        float p0, p1, p2, p3;
        {
            int h = h4*4;
            p0 = fmaxf(fmaf(mag, ws[h+0], fmaf(sa, ws[64+h+0], fmaf(ca, ws[128+h+0], fmaf(fr, ws[192+h+0], bs[h+0])))), 0.f);
            p1 = fmaxf(fmaf(mag, ws[h+1], fmaf(sa, ws[64+h+1], fmaf(ca, ws[128+h+1], fmaf(fr, ws[192+h+1], bs[h+1])))), 0.f);
            p2 = fmaxf(fmaf(mag, ws[h+2], fmaf(sa, ws[64+h+2], fmaf(ca, ws[128+h+2], fmaf(fr, ws[192+h+2], bs[h+2])))), 0.f);
            p3 = fmaxf(fmaf(mag, ws[h+3], fmaf(sa, ws[64+h+3], fmaf(ca, ws[128+h+3], fmaf(fr, ws[192+h+3], bs[h+3])))), 0.f);
        }
        dm = fmaf(p0,u.x, fmaf(p1,u.y, fmaf(p2,u.z, fmaf(p3,u.w, dm))));
        dp = fmaf(p0,v.x, fmaf(p1,v.y, fmaf(p2,v.z, fmaf(p3,v.w, dp))));
    }
    float mval = fmaxf(dm + mb[k], 0.f);
    float ph = 6.283185307179586f / (1.f + expf(-(dp + pb[k])));
    float sp, cp;
    sincosf(ph, &sp, &cp);
    float w = g_w[gidx];
    g_wfRe[fidx] = fmaf(w, mval*cp - re, re);
    g_wfIm[fidx] = fmaf(w, mval*sp - im, im);
}

// ---------------- K6: irfft(ortho) + residual + LayerNorm ----------------
__global__ __launch_bounds__(256) void k6_irfft(const float* __restrict__ x,
                                                const float* __restrict__ gamma_, const float* __restrict__ beta_,
                                                float* __restrict__ out){
    __shared__ float wr_sh[NFF*FF];
    __shared__ float wi_sh[NFF*FF];
    __shared__ float ct[HH];
    int b = blockIdx.x, tid = threadIdx.x;
    const float sc = 0.044194173824159216f;
    for(int i=tid;i<NFF*FF;i+=256){
        int k = i / FF;
        float alpha = (k==0 || k==256) ? sc : 2.0f*sc;
        wr_sh[i] = g_wfRe[b*NFF*FF + i] * alpha;
        wi_sh[i] = g_wfIm[b*NFF*FF + i] * alpha;
    }
    for(int i=tid;i<HH;i+=256) ct[i]=cospif((float)i*(1.0f/256.0f));
    __syncthreads();
    int f = tid & 15, tg = tid >> 4;
    float acc[32];
    #pragma unroll
    for(int i=0;i<32;i++) acc[i]=0.f;
    for(int k=0;k<NFF;k++){
        float wr = wr_sh[k*FF+f], wi = wi_sh[k*FF+f];
        int idx  = (k*tg)&511;
        int step = (k<<4)&511;
        #pragma unroll
        for(int i=0;i<32;i++){
            acc[i] = fmaf(wr, ct[idx], fmaf(-wi, ct[(idx+384)&511], acc[i]));
            idx = (idx+step)&511;
        }
    }
    float gm = gamma_[f], bt = beta_[f];
    #pragma unroll
    for(int i=0;i<32;i++){
        int t = tg + (i<<4);
        float y = acc[i] + x[((size_t)b*HH + t)*FF + f];
        float s = y, s2 = y*y;
        #pragma unroll
        for(int off=8; off>0; off>>=1){
            s  += __shfl_xor_sync(0xffffffffu, s,  off, 16);
            s2 += __shfl_xor_sync(0xffffffffu, s2, off, 16);
        }
        float mu  = s  * (1.0f/16.0f);
        float var = s2 * (1.0f/16.0f) - mu*mu;
        out[((size_t)b*HH + t)*FF + f] = (y - mu) * rsqrtf(var + 1e-5f) * gm + bt;
    }
}

// ---------------- launch ----------------
extern "C" void kernel_launch(void* const* d_in, const int* in_sizes, int n_in,
                              void* d_out, int out_size){
    const float* x   = (const float*)d_in[0];
    const float* Wp  = (const float*)d_in[1];
    const float* bp  = (const float*)d_in[2];
    const float* Wg  = (const float*)d_in[3];
    const float* bg  = (const float*)d_in[4];
    const float* mw  = (const float*)d_in[5];
    const float* mb  = (const float*)d_in[6];
    const float* pw  = (const float*)d_in[7];
    const float* pb  = (const float*)d_in[8];
    const float* gam = (const float*)d_in[9];
    const float* bet = (const float*)d_in[10];
    float* out = (float*)d_out;

    cudaFuncSetAttribute(k4_gemm, cudaFuncAttributeMaxDynamicSharedMemorySize, SMEM_K4);

    k0_sum <<<(BB*HH+255)/256, 256>>>(x);
    k1_csd <<<BB, 256>>>();
    k2_fft <<<BB, 256>>>(x);
    k3_proj<<<(BB*NFF*FF+255)/256, 256>>>(Wp, bp);
    dim3 gt(KDIM/32, (NB+31)/32);
    k4t    <<<gt, 256>>>(Wg);
    dim3 g4(MG/BM4, 3);
    k4_gemm<<<g4, 128, SMEM_K4>>>(bg);
    k5_blend<<<(MG*NFF+255)/256, 256>>>(mw, mb, pw, pb, Wp, bp);
    k6_irfft<<<BB, 256>>>(x, gam, bet, out);
}